// round 6
// baseline (speedup 1.0000x reference)
#include <cuda_runtime.h>
#include <math.h>

#define S    64
#define NF   196608
#define HD   128
#define K2   (2*NF)
#define NSUB (NF/32)   // 6144 k-subtiles of 32

// Scratch (device globals — no allocation allowed)
__device__ float g_U[S*HD];     // U[t*HD+h] = (W_z @ z_t)[h]
__device__ float g_M[HD*HD];    // g_M[h*HD+c] = (W_p @ fc2_w)[h][c]  (row-major for coalesced warp-per-row)
__device__ float g_v[HD];       // W_p @ fc2_b
__device__ float g_w0[HD];      // W_p @ prev_gen0
__device__ float g_H2[S*HD];    // h2 state per step

__device__ __forceinline__ float sigm(float x) { return 1.f / (1.f + expf(-x)); }

// ---------------- zero the atomic accumulators ----------------
__global__ void k_zero() {
    int n = S*HD + HD*HD + 2*HD;
    for (int i = blockIdx.x*blockDim.x + threadIdx.x; i < n; i += gridDim.x*blockDim.x) {
        if (i < S*HD)               g_U[i] = 0.f;
        else if (i < S*HD + HD*HD)  g_M[i - S*HD] = 0.f;
        else if (i < S*HD + HD*HD + HD) g_v[i - S*HD - HD*HD] = 0.f;
        else                        g_w0[i - S*HD - HD*HD - HD] = 0.f;
    }
}

// ---------------- GEMM 1: U[128 x 64] = W_z[128,K] * Z^T[K,64] (split-K, NT) ----------------
__global__ void __launch_bounds__(256, 2) k_gemm_u(const float* __restrict__ fc1w,
                                                   const float* __restrict__ z) {
    __shared__ float As[128*33];
    __shared__ float Zs[64*33];
    int tid = threadIdx.x;
    int ty = tid >> 4, tx = tid & 15;
    float acc[8][4];
    #pragma unroll
    for (int r = 0; r < 8; r++)
        #pragma unroll
        for (int c = 0; c < 4; c++) acc[r][c] = 0.f;

    for (int st = blockIdx.x; st < NSUB; st += gridDim.x) {
        int kb = st << 5;
        for (int idx = tid; idx < 128*32; idx += 256) {
            int row = idx >> 5, kk = idx & 31;
            As[row*33 + kk] = fc1w[row*K2 + kb + kk];
        }
        for (int idx = tid; idx < 64*32; idx += 256) {
            int t = idx >> 5, kk = idx & 31;
            Zs[t*33 + kk] = z[t*NF + kb + kk];
        }
        __syncthreads();
        #pragma unroll
        for (int kk = 0; kk < 32; kk++) {
            float a[8], b[4];
            #pragma unroll
            for (int r = 0; r < 8; r++) a[r] = As[(ty + 16*r)*33 + kk];
            #pragma unroll
            for (int c = 0; c < 4; c++) b[c] = Zs[(tx + 16*c)*33 + kk];
            #pragma unroll
            for (int r = 0; r < 8; r++)
                #pragma unroll
                for (int c = 0; c < 4; c++) acc[r][c] += a[r]*b[c];
        }
        __syncthreads();
    }
    #pragma unroll
    for (int r = 0; r < 8; r++)
        #pragma unroll
        for (int c = 0; c < 4; c++)
            atomicAdd(&g_U[(tx + 16*c)*HD + (ty + 16*r)], acc[r][c]);
}

// ------- GEMM 2: M[128 x 128] = W_p[128,K] * fc2_w[K,128] (+ W_p@fc2_b, W_p@pg0) -------
__global__ void __launch_bounds__(256, 2) k_gemm_m(const float* __restrict__ fc1w,
                                                   const float* __restrict__ fc2w,
                                                   const float* __restrict__ fc2b,
                                                   const float* __restrict__ pg0) {
    __shared__ float As[128*33];
    __shared__ float Bs[32*128];
    __shared__ float Es[64];
    int tid = threadIdx.x;
    int ty = tid >> 4, tx = tid & 15;
    int erow = tid & 127, ewhich = tid >> 7;   // which: 0 -> fc2_b dot, 1 -> pg0 dot
    float acc[8][8];
    float accE = 0.f;
    #pragma unroll
    for (int r = 0; r < 8; r++)
        #pragma unroll
        for (int c = 0; c < 8; c++) acc[r][c] = 0.f;

    for (int st = blockIdx.x; st < NSUB; st += gridDim.x) {
        int kb = st << 5;
        for (int idx = tid; idx < 128*32; idx += 256) {
            int row = idx >> 5, kk = idx & 31;
            As[row*33 + kk] = fc1w[row*K2 + NF + kb + kk];
        }
        for (int idx = tid; idx < 32*128; idx += 256) {
            int kk = idx >> 7, c = idx & 127;
            Bs[kk*128 + c] = fc2w[(kb + kk)*128 + c];
        }
        if (tid < 64) Es[tid] = (tid < 32) ? fc2b[kb + tid] : pg0[kb + (tid - 32)];
        __syncthreads();
        #pragma unroll
        for (int kk = 0; kk < 32; kk++) {
            float a[8], b[8];
            #pragma unroll
            for (int r = 0; r < 8; r++) a[r] = As[(ty + 16*r)*33 + kk];
            #pragma unroll
            for (int c = 0; c < 8; c++) b[c] = Bs[kk*128 + tx + 16*c];
            #pragma unroll
            for (int r = 0; r < 8; r++)
                #pragma unroll
                for (int c = 0; c < 8; c++) acc[r][c] += a[r]*b[c];
            accE += As[erow*33 + kk] * Es[ewhich*32 + kk];
        }
        __syncthreads();
    }
    #pragma unroll
    for (int r = 0; r < 8; r++)
        #pragma unroll
        for (int c = 0; c < 8; c++)
            atomicAdd(&g_M[(ty + 16*r)*HD + (tx + 16*c)], acc[r][c]);   // row-major M
    atomicAdd(ewhich ? &g_w0[erow] : &g_v[erow], accE);
}

// ---------------- Phase 2: the 64-step recurrent scan ----------------
// v2: warp-per-row coalesced weight loads + shfl butterfly reduction.
// Each LDG.128 warp-instruction now covers one contiguous 512B row slice
// (4 wavefronts) instead of 32 scattered lines (32 wavefronts) -> 8x less
// L1tex pressure; per-step memory floor ~8.3K cyc instead of ~65K.
__global__ void __launch_bounds__(512) k_scan(
    const float* __restrict__ h1_in, const float* __restrict__ c1_in,
    const float* __restrict__ h2_in, const float* __restrict__ c2_in,
    const float* __restrict__ fc1b,
    const float* __restrict__ wih1, const float* __restrict__ whh1,
    const float* __restrict__ bih1, const float* __restrict__ bhh1,
    const float* __restrict__ wih2, const float* __restrict__ whh2,
    const float* __restrict__ bih2, const float* __restrict__ bhh2,
    float* __restrict__ out, int out_size)
{
    __shared__ __align__(16) float xs[HD], h1s[HD], c1s[HD], h2s[HD], c2s[HD];
    __shared__ float gs[4*HD];
    __shared__ float b1s[4*HD], b2s[4*HD], xbv[HD], xbw0[HD];
    int tid  = threadIdx.x;
    int warp = tid >> 5, lane = tid & 31;

    for (int i = tid; i < 4*HD; i += 512) { b1s[i] = bih1[i] + bhh1[i]; b2s[i] = bih2[i] + bhh2[i]; }
    if (tid < HD) {
        h1s[tid] = h1_in[tid]; c1s[tid] = c1_in[tid];
        h2s[tid] = h2_in[tid]; c2s[tid] = c2_in[tid];
        xbv[tid]  = fc1b[tid] + g_v[tid];
        xbw0[tid] = fc1b[tid] + g_w0[tid];
    }
    __syncthreads();

    for (int t = 0; t < S; t++) {
        // ---- x_t = relu(U_t + M@h2 + fc1_b + v)  (t=0: uses w0, no M term) ----
        if (t == 0) {
            if (tid < HD) xs[tid] = fmaxf(g_U[tid] + xbw0[tid], 0.f);
        } else {
            float4 hv = ((const float4*)h2s)[lane];
            #pragma unroll
            for (int i = 0; i < 8; i++) {
                int r = warp*8 + i;
                float4 m = ((const float4*)(g_M + r*HD))[lane];
                float p = m.x*hv.x + m.y*hv.y + m.z*hv.z + m.w*hv.w;
                #pragma unroll
                for (int off = 16; off; off >>= 1) p += __shfl_xor_sync(0xffffffffu, p, off);
                if (lane == 0) xs[r] = fmaxf(p + g_U[t*HD + r] + xbv[r], 0.f);
            }
        }
        __syncthreads();

        // ---- LSTM1 gates: 512 rows, 32 per warp, warp-per-row ----
        {
            float4 xv = ((const float4*)xs)[lane];
            float4 hv = ((const float4*)h1s)[lane];
            #pragma unroll 4
            for (int i = 0; i < 32; i++) {
                int r = warp*32 + i;
                float4 wi = ((const float4*)(wih1 + r*HD))[lane];
                float4 wh = ((const float4*)(whh1 + r*HD))[lane];
                float p = wi.x*xv.x + wi.y*xv.y + wi.z*xv.z + wi.w*xv.w
                        + wh.x*hv.x + wh.y*hv.y + wh.z*hv.z + wh.w*hv.w;
                #pragma unroll
                for (int off = 16; off; off >>= 1) p += __shfl_xor_sync(0xffffffffu, p, off);
                if (lane == 0) gs[r] = p + b1s[r];
            }
        }
        __syncthreads();
        if (tid < HD) {
            float gi = gs[tid], gf = gs[HD+tid], gg = gs[2*HD+tid], go = gs[3*HD+tid];
            float c = sigm(gf)*c1s[tid] + sigm(gi)*tanhf(gg);
            c1s[tid] = c;
            h1s[tid] = sigm(go)*tanhf(c);
        }
        __syncthreads();

        // ---- LSTM2 gates (input = h1) ----
        {
            float4 xv = ((const float4*)h1s)[lane];
            float4 hv = ((const float4*)h2s)[lane];
            #pragma unroll 4
            for (int i = 0; i < 32; i++) {
                int r = warp*32 + i;
                float4 wi = ((const float4*)(wih2 + r*HD))[lane];
                float4 wh = ((const float4*)(whh2 + r*HD))[lane];
                float p = wi.x*xv.x + wi.y*xv.y + wi.z*xv.z + wi.w*xv.w
                        + wh.x*hv.x + wh.y*hv.y + wh.z*hv.z + wh.w*hv.w;
                #pragma unroll
                for (int off = 16; off; off >>= 1) p += __shfl_xor_sync(0xffffffffu, p, off);
                if (lane == 0) gs[r] = p + b2s[r];
            }
        }
        __syncthreads();
        if (tid < HD) {
            float gi = gs[tid], gf = gs[HD+tid], gg = gs[2*HD+tid], go = gs[3*HD+tid];
            float c = sigm(gf)*c2s[tid] + sigm(gi)*tanhf(gg);
            c2s[tid] = c;
            float h = sigm(go)*tanhf(c);
            h2s[tid] = h;
            g_H2[t*HD + tid] = h;
        }
        __syncthreads();
    }

    if (out_size >= S*NF + 4*HD && tid < HD) {
        out[S*NF + 0*HD + tid] = h1s[tid];
        out[S*NF + 1*HD + tid] = c1s[tid];
        out[S*NF + 2*HD + tid] = h2s[tid];
        out[S*NF + 3*HD + tid] = c2s[tid];
    }
}

// ------- GEMM 3: out[t,k] = fc2_w[k,:] . h2_t + fc2_b[k] + y[t,k] (NT, K=128) -------
__global__ void __launch_bounds__(256) k_out(const float* __restrict__ fc2w,
                                             const float* __restrict__ fc2b,
                                             const float* __restrict__ y,
                                             float* __restrict__ out) {
    __shared__ __align__(16) float H2s[S*HD];
    int tid = threadIdx.x;
    for (int i = tid; i < S*HD; i += 256) H2s[i] = g_H2[i];
    __syncthreads();

    int k = blockIdx.x*256 + tid;
    const float4* w4 = (const float4*)(fc2w + k*HD);
    const float4* h4 = (const float4*)H2s;
    float acc[S];
    #pragma unroll
    for (int t = 0; t < S; t++) acc[t] = 0.f;

    #pragma unroll 4
    for (int j = 0; j < 32; j++) {
        float4 w = w4[j];
        #pragma unroll
        for (int t = 0; t < S; t++) {
            float4 h = h4[t*32 + j];
            acc[t] += w.x*h.x + w.y*h.y + w.z*h.z + w.w*h.w;
        }
    }
    float b = fc2b[k];
    #pragma unroll 4
    for (int t = 0; t < S; t++)
        out[t*NF + k] = acc[t] + b + y[t*NF + k];
}

// ---------------- launcher ----------------
extern "C" void kernel_launch(void* const* d_in, const int* in_sizes, int n_in,
                              void* d_out, int out_size) {
    const float* z    = (const float*)d_in[0];
    const float* y    = (const float*)d_in[1];
    const float* pg0  = (const float*)d_in[2];
    const float* h1   = (const float*)d_in[3];
    const float* c1   = (const float*)d_in[4];
    const float* h2   = (const float*)d_in[5];
    const float* c2   = (const float*)d_in[6];
    const float* fc1w = (const float*)d_in[7];
    const float* fc1b = (const float*)d_in[8];
    const float* wih1 = (const float*)d_in[9];
    const float* whh1 = (const float*)d_in[10];
    const float* bih1 = (const float*)d_in[11];
    const float* bhh1 = (const float*)d_in[12];
    const float* wih2 = (const float*)d_in[13];
    const float* whh2 = (const float*)d_in[14];
    const float* bih2 = (const float*)d_in[15];
    const float* bhh2 = (const float*)d_in[16];
    const float* fc2w = (const float*)d_in[17];
    const float* fc2b = (const float*)d_in[18];
    float* out = (float*)d_out;

    k_zero<<<32, 256>>>();
    k_gemm_u<<<296, 256>>>(fc1w, z);
    k_gemm_m<<<296, 256>>>(fc1w, fc2w, fc2b, pg0);
    k_scan<<<1, 512>>>(h1, c1, h2, c2, fc1b,
                       wih1, whh1, bih1, bhh1,
                       wih2, whh2, bih2, bhh2,
                       out, out_size);
    k_out<<<768, 256>>>(fc2w, fc2b, y, out);
}

// round 7
// speedup vs baseline: 2.0196x; 2.0196x over previous
#include <cuda_runtime.h>
#include <math.h>
#include <stdint.h>

#define S    64
#define NF   196608
#define HD   128
#define K2   (2*NF)
#define NSUB (NF/32)   // 6144 k-subtiles of 32
#define CL   8         // scan cluster size

// Scratch (device globals — no allocation allowed)
__device__ float g_U[S*HD];     // U[t*HD+h] = (W_z @ z_t)[h]
__device__ float g_M[HD*HD];    // g_M[h*HD+c] = (W_p @ fc2_w)[h][c] (row-major)
__device__ float g_v[HD];       // W_p @ fc2_b
__device__ float g_w0[HD];      // W_p @ prev_gen0
__device__ float g_H2T[HD*S];   // h2 states, TRANSPOSED: g_H2T[j*S + t]

__device__ __forceinline__ float sigm(float x) { return 1.f / (1.f + expf(-x)); }

// ---- f32x2 packed fp32 helpers (PTX-only; ptxas won't auto-fuse) ----
__device__ __forceinline__ unsigned long long pack2(float a) {
    unsigned long long r;
    asm("mov.b64 %0, {%1, %1};" : "=l"(r) : "f"(a));
    return r;
}
__device__ __forceinline__ void fma2(unsigned long long& d, unsigned long long a, unsigned long long b) {
    asm("fma.rn.f32x2 %0, %1, %2, %0;" : "+l"(d) : "l"(a), "l"(b));
}
__device__ __forceinline__ float lo2(unsigned long long v) { return __uint_as_float((unsigned)(v & 0xffffffffu)); }
__device__ __forceinline__ float hi2(unsigned long long v) { return __uint_as_float((unsigned)(v >> 32)); }

// ---- cluster / DSMEM helpers ----
__device__ __forceinline__ uint32_t smem_u32(const void* p) {
    uint32_t a;
    asm("{ .reg .u64 t; cvta.to.shared.u64 t, %1; cvt.u32.u64 %0, t; }" : "=r"(a) : "l"(p));
    return a;
}
__device__ __forceinline__ uint32_t ctarank() {
    uint32_t r; asm("mov.u32 %0, %%cluster_ctarank;" : "=r"(r)); return r;
}
__device__ __forceinline__ uint32_t mapa_u32(uint32_t addr, uint32_t rank) {
    uint32_t r; asm("mapa.shared::cluster.u32 %0, %1, %2;" : "=r"(r) : "r"(addr), "r"(rank));
    return r;
}
__device__ __forceinline__ void st_cluster(uint32_t addr, float v) {
    asm volatile("st.shared::cluster.f32 [%0], %1;" :: "r"(addr), "f"(v) : "memory");
}
#define CLUSTER_BAR() do { \
    asm volatile("barrier.cluster.arrive.aligned;" ::: "memory"); \
    asm volatile("barrier.cluster.wait.aligned;"   ::: "memory"); \
} while (0)

// ---------------- zero the atomic accumulators ----------------
__global__ void k_zero() {
    int n = S*HD + HD*HD + 2*HD;
    for (int i = blockIdx.x*blockDim.x + threadIdx.x; i < n; i += gridDim.x*blockDim.x) {
        if (i < S*HD)               g_U[i] = 0.f;
        else if (i < S*HD + HD*HD)  g_M[i - S*HD] = 0.f;
        else if (i < S*HD + HD*HD + HD) g_v[i - S*HD - HD*HD] = 0.f;
        else                        g_w0[i - S*HD - HD*HD - HD] = 0.f;
    }
}

// ---------------- GEMM 1: U[128 x 64] = W_z[128,K] * Z^T[K,64] (split-K, NT) ----------------
__global__ void __launch_bounds__(256, 2) k_gemm_u(const float* __restrict__ fc1w,
                                                   const float* __restrict__ z) {
    __shared__ float As[128*33];
    __shared__ float Zs[64*33];
    int tid = threadIdx.x;
    int ty = tid >> 4, tx = tid & 15;
    float acc[8][4];
    #pragma unroll
    for (int r = 0; r < 8; r++)
        #pragma unroll
        for (int c = 0; c < 4; c++) acc[r][c] = 0.f;

    for (int st = blockIdx.x; st < NSUB; st += gridDim.x) {
        int kb = st << 5;
        for (int idx = tid; idx < 128*32; idx += 256) {
            int row = idx >> 5, kk = idx & 31;
            As[row*33 + kk] = fc1w[row*K2 + kb + kk];
        }
        for (int idx = tid; idx < 64*32; idx += 256) {
            int t = idx >> 5, kk = idx & 31;
            Zs[t*33 + kk] = z[t*NF + kb + kk];
        }
        __syncthreads();
        #pragma unroll
        for (int kk = 0; kk < 32; kk++) {
            float a[8], b[4];
            #pragma unroll
            for (int r = 0; r < 8; r++) a[r] = As[(ty + 16*r)*33 + kk];
            #pragma unroll
            for (int c = 0; c < 4; c++) b[c] = Zs[(tx + 16*c)*33 + kk];
            #pragma unroll
            for (int r = 0; r < 8; r++)
                #pragma unroll
                for (int c = 0; c < 4; c++) acc[r][c] += a[r]*b[c];
        }
        __syncthreads();
    }
    #pragma unroll
    for (int r = 0; r < 8; r++)
        #pragma unroll
        for (int c = 0; c < 4; c++)
            atomicAdd(&g_U[(tx + 16*c)*HD + (ty + 16*r)], acc[r][c]);
}

// ------- GEMM 2 (f32x2): M[128x128] = W_p[128,K] * fc2_w[K,128] (+ W_p@fc2_b, W_p@pg0) -------
// Thread (ty,tx): rows ty+16r (r<8), column PAIRS {2tx+32c2, 2tx+32c2+1} (c2<4).
__global__ void __launch_bounds__(256, 2) k_gemm_m(const float* __restrict__ fc1w,
                                                   const float* __restrict__ fc2w,
                                                   const float* __restrict__ fc2b,
                                                   const float* __restrict__ pg0) {
    __shared__ float As[128*33];
    __shared__ __align__(16) float Bs[32*128];
    __shared__ float Es[64];
    int tid = threadIdx.x;
    int ty = tid >> 4, tx = tid & 15;
    int erow = tid & 127, ewhich = tid >> 7;
    unsigned long long acc2[8][4];
    float accE = 0.f;
    #pragma unroll
    for (int r = 0; r < 8; r++)
        #pragma unroll
        for (int c = 0; c < 4; c++) acc2[r][c] = 0ull;

    for (int st = blockIdx.x; st < NSUB; st += gridDim.x) {
        int kb = st << 5;
        for (int idx = tid; idx < 128*32; idx += 256) {
            int row = idx >> 5, kk = idx & 31;
            As[row*33 + kk] = fc1w[row*K2 + NF + kb + kk];
        }
        for (int idx = tid; idx < 32*128; idx += 256) {
            int kk = idx >> 7, c = idx & 127;
            Bs[kk*128 + c] = fc2w[(kb + kk)*128 + c];
        }
        if (tid < 64) Es[tid] = (tid < 32) ? fc2b[kb + tid] : pg0[kb + (tid - 32)];
        __syncthreads();
        #pragma unroll
        for (int kk = 0; kk < 32; kk++) {
            unsigned long long pa[8];
            #pragma unroll
            for (int r = 0; r < 8; r++) pa[r] = pack2(As[(ty + 16*r)*33 + kk]);
            #pragma unroll
            for (int c2 = 0; c2 < 4; c2++) {
                unsigned long long pb = *(const unsigned long long*)(&Bs[kk*128 + 2*tx + 32*c2]);
                #pragma unroll
                for (int r = 0; r < 8; r++) fma2(acc2[r][c2], pa[r], pb);
            }
            accE += As[erow*33 + kk] * Es[ewhich*32 + kk];
        }
        __syncthreads();
    }
    #pragma unroll
    for (int r = 0; r < 8; r++)
        #pragma unroll
        for (int c2 = 0; c2 < 4; c2++) {
            int col = 2*tx + 32*c2;
            atomicAdd(&g_M[(ty + 16*r)*HD + col],     lo2(acc2[r][c2]));
            atomicAdd(&g_M[(ty + 16*r)*HD + col + 1], hi2(acc2[r][c2]));
        }
    atomicAdd(ewhich ? &g_w0[erow] : &g_v[erow], accE);
}

// ---------------- Phase 2: cluster-resident recurrent scan ----------------
// 8-CTA cluster; CTA r owns h-elements [16r,16r+16): 64 gate rows per LSTM
// (wi+wh = 64KB each LSTM) + 16 M rows, ALL SMEM-resident for the whole scan.
// 128-float x/h1/h2 vectors broadcast via DSMEM stores + barrier.cluster.
// h1/h2 double-buffered (write buf p^1 while peers read buf p).
#define OFS_WI1 0
#define OFS_WH1 8192
#define OFS_WI2 16384
#define OFS_WH2 24576
#define OFS_M   32768
#define OFS_U   34816
#define OFS_X   35840
#define OFS_H1  35968   /* 2 x 128 */
#define OFS_H2  36224   /* 2 x 128 */
#define OFS_G   36480
#define OFS_B1  36544
#define OFS_B2  36608
#define OFS_XB  36672
#define OFS_XB0 36688
#define OFS_C1  36704
#define OFS_C2  36720
#define SCAN_SMEM_FLOATS 36736
#define SCAN_SMEM_BYTES  (SCAN_SMEM_FLOATS*4)

__global__ void __launch_bounds__(256, 1) __cluster_dims__(CL, 1, 1)
k_scan(const float* __restrict__ h1_in, const float* __restrict__ c1_in,
       const float* __restrict__ h2_in, const float* __restrict__ c2_in,
       const float* __restrict__ fc1b,
       const float* __restrict__ wih1, const float* __restrict__ whh1,
       const float* __restrict__ bih1, const float* __restrict__ bhh1,
       const float* __restrict__ wih2, const float* __restrict__ whh2,
       const float* __restrict__ bih2, const float* __restrict__ bhh2,
       float* __restrict__ out, int out_size)
{
    extern __shared__ __align__(16) float sm[];
    const int tid  = threadIdx.x;
    const int warp = tid >> 5, lane = tid & 31;
    const uint32_t rank = ctarank();
    const uint32_t sbase = smem_u32(sm);

    // ---- load resident weights (once) ----
    for (int idx = tid; idx < 64*128; idx += 256) {
        int l = idx >> 7, k = idx & 127;
        int gr = ((l >> 4) << 7) + (int)rank*16 + (l & 15);   // gate*128 + elem
        sm[OFS_WI1 + idx] = wih1[gr*HD + k];
        sm[OFS_WH1 + idx] = whh1[gr*HD + k];
        sm[OFS_WI2 + idx] = wih2[gr*HD + k];
        sm[OFS_WH2 + idx] = whh2[gr*HD + k];
    }
    for (int idx = tid; idx < 16*128; idx += 256) {
        int l = idx >> 7, k = idx & 127;
        sm[OFS_M + idx] = g_M[((int)rank*16 + l)*HD + k];
    }
    for (int idx = tid; idx < S*16; idx += 256) {
        int t = idx >> 4, j = idx & 15;
        sm[OFS_U + idx] = g_U[t*HD + (int)rank*16 + j];
    }
    if (tid < 64) {
        int gr = ((tid >> 4) << 7) + (int)rank*16 + (tid & 15);
        sm[OFS_B1 + tid] = bih1[gr] + bhh1[gr];
        sm[OFS_B2 + tid] = bih2[gr] + bhh2[gr];
    }
    if (tid < 16) {
        int e = (int)rank*16 + tid;
        sm[OFS_XB  + tid] = fc1b[e] + g_v[e];
        sm[OFS_XB0 + tid] = fc1b[e] + g_w0[e];
        sm[OFS_C1  + tid] = c1_in[e];
        sm[OFS_C2  + tid] = c2_in[e];
    }
    if (tid < HD) {
        sm[OFS_H1 + tid] = h1_in[tid];   // buffer 0
        sm[OFS_H2 + tid] = h2_in[tid];   // buffer 0
    }
    __syncthreads();
    CLUSTER_BAR();

    for (int t = 0; t < S; t++) {
        const int p = t & 1;

        // ---- phase X: x = relu(U_t + M@h2_{t-1} + fc1b + v) (16 elems/CTA) ----
        if (t == 0) {
            if (tid < 16)
                sm[OFS_X + (int)rank*16 + tid] = fmaxf(sm[OFS_U + tid] + sm[OFS_XB0 + tid], 0.f);
        } else {
            float4 hv = ((const float4*)(sm + OFS_H2 + p*HD))[lane];
            #pragma unroll
            for (int ii = 0; ii < 2; ii++) {
                int l = warp*2 + ii;                       // 0..15
                float4 m = ((const float4*)(sm + OFS_M + l*HD))[lane];
                float pd = m.x*hv.x + m.y*hv.y + m.z*hv.z + m.w*hv.w;
                #pragma unroll
                for (int off = 16; off; off >>= 1) pd += __shfl_xor_sync(0xffffffffu, pd, off);
                if (lane == 0)
                    sm[OFS_X + (int)rank*16 + l] = fmaxf(pd + sm[OFS_U + t*16 + l] + sm[OFS_XB + l], 0.f);
            }
        }
        __syncthreads();
        if (tid < 128) {   // broadcast own x slice to all CTAs
            int e = (int)rank*16 + (tid >> 3);
            st_cluster(mapa_u32(sbase + (uint32_t)(OFS_X + e)*4u, (uint32_t)(tid & 7)), sm[OFS_X + e]);
        }
        CLUSTER_BAR();

        // ---- LSTM1: 64 rows/CTA (8/warp); reads full x + h1[p] ----
        {
            float4 xv = ((const float4*)(sm + OFS_X))[lane];
            float4 hv = ((const float4*)(sm + OFS_H1 + p*HD))[lane];
            #pragma unroll
            for (int i = 0; i < 8; i++) {
                int l = warp*8 + i;
                float4 wi = ((const float4*)(sm + OFS_WI1 + l*HD))[lane];
                float4 wh = ((const float4*)(sm + OFS_WH1 + l*HD))[lane];
                float pd = wi.x*xv.x + wi.y*xv.y + wi.z*xv.z + wi.w*xv.w
                         + wh.x*hv.x + wh.y*hv.y + wh.z*hv.z + wh.w*hv.w;
                #pragma unroll
                for (int off = 16; off; off >>= 1) pd += __shfl_xor_sync(0xffffffffu, pd, off);
                if (lane == 0) sm[OFS_G + l] = pd + sm[OFS_B1 + l];
            }
        }
        __syncthreads();
        if (tid < 16) {
            float gi = sm[OFS_G + tid],      gf = sm[OFS_G + 16 + tid];
            float gg = sm[OFS_G + 32 + tid], go = sm[OFS_G + 48 + tid];
            float c = sigm(gf)*sm[OFS_C1 + tid] + sigm(gi)*tanhf(gg);
            sm[OFS_C1 + tid] = c;
            sm[OFS_H1 + (p^1)*HD + (int)rank*16 + tid] = sigm(go)*tanhf(c);
        }
        __syncthreads();
        if (tid < 128) {
            int e = (int)rank*16 + (tid >> 3);
            st_cluster(mapa_u32(sbase + (uint32_t)(OFS_H1 + (p^1)*HD + e)*4u, (uint32_t)(tid & 7)),
                       sm[OFS_H1 + (p^1)*HD + e]);
        }
        CLUSTER_BAR();

        // ---- LSTM2: input h1[p^1], hidden h2[p] ----
        {
            float4 xv = ((const float4*)(sm + OFS_H1 + (p^1)*HD))[lane];
            float4 hv = ((const float4*)(sm + OFS_H2 + p*HD))[lane];
            #pragma unroll
            for (int i = 0; i < 8; i++) {
                int l = warp*8 + i;
                float4 wi = ((const float4*)(sm + OFS_WI2 + l*HD))[lane];
                float4 wh = ((const float4*)(sm + OFS_WH2 + l*HD))[lane];
                float pd = wi.x*xv.x + wi.y*xv.y + wi.z*xv.z + wi.w*xv.w
                         + wh.x*hv.x + wh.y*hv.y + wh.z*hv.z + wh.w*hv.w;
                #pragma unroll
                for (int off = 16; off; off >>= 1) pd += __shfl_xor_sync(0xffffffffu, pd, off);
                if (lane == 0) sm[OFS_G + l] = pd + sm[OFS_B2 + l];
            }
        }
        __syncthreads();
        if (tid < 16) {
            float gi = sm[OFS_G + tid],      gf = sm[OFS_G + 16 + tid];
            float gg = sm[OFS_G + 32 + tid], go = sm[OFS_G + 48 + tid];
            float c = sigm(gf)*sm[OFS_C2 + tid] + sigm(gi)*tanhf(gg);
            sm[OFS_C2 + tid] = c;
            float h = sigm(go)*tanhf(c);
            int e = (int)rank*16 + tid;
            sm[OFS_H2 + (p^1)*HD + e] = h;
            g_H2T[e*S + t] = h;                      // transposed for k_out
        }
        __syncthreads();
        if (tid < 128) {
            int e = (int)rank*16 + (tid >> 3);
            st_cluster(mapa_u32(sbase + (uint32_t)(OFS_H2 + (p^1)*HD + e)*4u, (uint32_t)(tid & 7)),
                       sm[OFS_H2 + (p^1)*HD + e]);
        }
        CLUSTER_BAR();
    }

    // final states live in buffer 0 (t=63 wrote p^1 = 0); c slices are local
    if (out_size >= S*NF + 4*HD && tid < 16) {
        int e = (int)rank*16 + tid;
        out[S*NF + 0*HD + e] = sm[OFS_H1 + e];
        out[S*NF + 1*HD + e] = sm[OFS_C1 + tid];
        out[S*NF + 2*HD + e] = sm[OFS_H2 + e];
        out[S*NF + 3*HD + e] = sm[OFS_C2 + tid];
    }
}

// ------- GEMM 3 (f32x2): out[t,k] = fc2_w[k,:] . h2_t + fc2_b[k] + y[t,k] -------
// H2 is transposed in SMEM ([k-dim j][t]) so t-PAIRS are contiguous -> ulonglong2 broadcasts.
__global__ void __launch_bounds__(256) k_out(const float* __restrict__ fc2w,
                                             const float* __restrict__ fc2b,
                                             const float* __restrict__ y,
                                             float* __restrict__ out) {
    __shared__ __align__(16) float H2T[HD*S];
    int tid = threadIdx.x;
    for (int i = tid; i < HD*S; i += 256) H2T[i] = g_H2T[i];
    __syncthreads();

    int k = blockIdx.x*256 + tid;
    const float4* w4 = (const float4*)(fc2w + k*HD);
    unsigned long long acc2[32];
    #pragma unroll
    for (int i = 0; i < 32; i++) acc2[i] = 0ull;

    #pragma unroll 2
    for (int j4 = 0; j4 < 32; j4++) {
        float4 w = w4[j4];
        float wc[4] = {w.x, w.y, w.z, w.w};
        #pragma unroll
        for (int cc = 0; cc < 4; cc++) {
            unsigned long long pw = pack2(wc[cc]);
            int j = j4*4 + cc;
            const ulonglong2* hp = (const ulonglong2*)(H2T + j*S);
            #pragma unroll
            for (int tq = 0; tq < 16; tq++) {
                ulonglong2 hh = hp[tq];
                fma2(acc2[2*tq],     pw, hh.x);
                fma2(acc2[2*tq + 1], pw, hh.y);
            }
        }
    }
    float b = fc2b[k];
    #pragma unroll 4
    for (int i = 0; i < 32; i++) {
        int t0 = 2*i;
        out[t0*NF + k]       = lo2(acc2[i]) + b + y[t0*NF + k];
        out[(t0 + 1)*NF + k] = hi2(acc2[i]) + b + y[(t0 + 1)*NF + k];
    }
}

// ---------------- launcher ----------------
extern "C" void kernel_launch(void* const* d_in, const int* in_sizes, int n_in,
                              void* d_out, int out_size) {
    const float* z    = (const float*)d_in[0];
    const float* y    = (const float*)d_in[1];
    const float* pg0  = (const float*)d_in[2];
    const float* h1   = (const float*)d_in[3];
    const float* c1   = (const float*)d_in[4];
    const float* h2   = (const float*)d_in[5];
    const float* c2   = (const float*)d_in[6];
    const float* fc1w = (const float*)d_in[7];
    const float* fc1b = (const float*)d_in[8];
    const float* wih1 = (const float*)d_in[9];
    const float* whh1 = (const float*)d_in[10];
    const float* bih1 = (const float*)d_in[11];
    const float* bhh1 = (const float*)d_in[12];
    const float* wih2 = (const float*)d_in[13];
    const float* whh2 = (const float*)d_in[14];
    const float* bih2 = (const float*)d_in[15];
    const float* bhh2 = (const float*)d_in[16];
    const float* fc2w = (const float*)d_in[17];
    const float* fc2b = (const float*)d_in[18];
    float* out = (float*)d_out;

    cudaFuncSetAttribute(k_scan, cudaFuncAttributeMaxDynamicSharedMemorySize, SCAN_SMEM_BYTES);

    k_zero<<<32, 256>>>();
    k_gemm_u<<<296, 256>>>(fc1w, z);
    k_gemm_m<<<296, 256>>>(fc1w, fc2w, fc2b, pg0);
    k_scan<<<CL, 256, SCAN_SMEM_BYTES>>>(h1, c1, h2, c2, fc1b,
                                         wih1, whh1, bih1, bhh1,
                                         wih2, whh2, bih2, bhh2,
                                         out, out_size);
    k_out<<<768, 256>>>(fc2w, fc2b, y, out);
}